// round 13
// baseline (speedup 1.0000x reference)
#include <cuda_runtime.h>
#include <cuda_fp16.h>
#include <math.h>
#include <stdint.h>

#define CDIM   1024
#define TSEQ   2048
#define BATCH  2
#define NHEAD  16
#define HDIM   64
#define MMEM   64
#define HIDDEN 4096

// ---------------- scratch (device globals; no allocation) ----------------
__device__ __half g_H    [BATCH*TSEQ*CDIM];
__device__ __half g_QKV  [BATCH*TSEQ*3*CDIM];
__device__ __half g_MEMP [MMEM*CDIM];
__device__ __half g_ATTN [BATCH*TSEQ*CDIM];
__device__ float  g_X1   [BATCH*TSEQ*CDIM];
__device__ __half g_H2   [BATCH*TSEQ*CDIM];
__device__ __half g_HID  [BATCH*TSEQ*HIDDEN];
__device__ __half g_WQKVT[3*CDIM*CDIM];
__device__ __half g_WOUTT[CDIM*CDIM];
__device__ __half g_WFC1T[HIDDEN*CDIM];
__device__ __half g_WFC2T[CDIM*HIDDEN];

__device__ __forceinline__ uint32_t smem_u32(const void* p) {
    uint32_t a;
    asm("{ .reg .u64 t; cvta.to.shared.u64 t, %1; cvt.u32.u64 %0, t; }" : "=r"(a) : "l"(p));
    return a;
}
__device__ __forceinline__ void cp16(uint32_t dst, const void* src) {
    asm volatile("cp.async.cg.shared.global [%0], [%1], 16;" :: "r"(dst), "l"(src));
}
__device__ __forceinline__ void mma_f16(float* c, uint32_t a0, uint32_t a1,
                                        uint32_t a2, uint32_t a3,
                                        uint32_t b0, uint32_t b1)
{
    asm volatile(
        "mma.sync.aligned.m16n8k16.row.col.f32.f16.f16.f32 "
        "{%0,%1,%2,%3}, {%4,%5,%6,%7}, {%8,%9}, {%0,%1,%2,%3};"
        : "+f"(c[0]), "+f"(c[1]), "+f"(c[2]), "+f"(c[3])
        : "r"(a0), "r"(a1), "r"(a2), "r"(a3), "r"(b0), "r"(b1));
}
__device__ __forceinline__ void ldsm4(uint32_t* r, uint32_t addr) {
    asm volatile("ldmatrix.sync.aligned.m8n8.x4.shared.b16 {%0,%1,%2,%3}, [%4];"
        : "=r"(r[0]), "=r"(r[1]), "=r"(r[2]), "=r"(r[3]) : "r"(addr));
}
__device__ __forceinline__ void ldsm4t(uint32_t* r, uint32_t addr) {
    asm volatile("ldmatrix.sync.aligned.m8n8.x4.trans.shared.b16 {%0,%1,%2,%3}, [%4];"
        : "=r"(r[0]), "=r"(r[1]), "=r"(r[2]), "=r"(r[3]) : "r"(addr));
}

// ---------------- LayerNorm body ----------------
__device__ __forceinline__ void ln_body(const float* __restrict__ x, const float* __restrict__ g,
                                        const float* __restrict__ b, __half* __restrict__ y,
                                        int row, int tid, float* red)
{
    const float4 v = ((const float4*)(x + (size_t)row * CDIM))[tid];
    float s  = v.x + v.y + v.z + v.w;
    float ss = v.x*v.x + v.y*v.y + v.z*v.z + v.w*v.w;
    #pragma unroll
    for (int off = 16; off; off >>= 1) {
        s  += __shfl_xor_sync(0xffffffffu, s,  off);
        ss += __shfl_xor_sync(0xffffffffu, ss, off);
    }
    if ((tid & 31) == 0) { red[tid >> 5] = s; red[8 + (tid >> 5)] = ss; }
    __syncthreads();
    if (tid == 0) {
        float ts = 0.f, tss = 0.f;
        #pragma unroll
        for (int w = 0; w < 8; w++) { ts += red[w]; tss += red[8 + w]; }
        red[16] = ts; red[17] = tss;
    }
    __syncthreads();
    const float mu  = red[16] * (1.f / CDIM);
    const float var = red[17] * (1.f / CDIM) - mu * mu;
    const float inv = rsqrtf(var + 1e-5f);
    const float4 gv = ((const float4*)g)[tid];
    const float4 bv = ((const float4*)b)[tid];
    __half2 h01 = __floats2half2_rn((v.x - mu) * inv * gv.x + bv.x,
                                    (v.y - mu) * inv * gv.y + bv.y);
    __half2 h23 = __floats2half2_rn((v.z - mu) * inv * gv.z + bv.z,
                                    (v.w - mu) * inv * gv.w + bv.w);
    __half2* yp = (__half2*)(y + (size_t)row * CDIM + tid * 4);
    yp[0] = h01; yp[1] = h23;
}

__global__ __launch_bounds__(256)
void ln_kernel(const float* __restrict__ x, const float* __restrict__ g,
               const float* __restrict__ b, __half* __restrict__ y)
{
    __shared__ float red[18];
    ln_body(x, g, b, y, blockIdx.x, threadIdx.x, red);
}

// ---------------- transpose body ----------------
__device__ __forceinline__ void transpose_body(const float* __restrict__ S, __half* __restrict__ D,
                                               int K, int N, int lb, int tid, char* buf)
{
    float (*t)[33] = (float(*)[33])buf;
    const int gx = N / 32;
    const int bx = (lb % gx) * 32;
    const int by = (lb / gx) * 32;
    const int x = tid & 31, y = tid >> 5;
    #pragma unroll
    for (int i = 0; i < 32; i += 8)
        t[y + i][x] = S[(size_t)(by + y + i) * N + bx + x];
    __syncthreads();
    #pragma unroll
    for (int i = 0; i < 32; i += 8)
        D[(size_t)(bx + y + i) * K + by + x] = __float2half_rn(t[x][y + i]);
}

// ---------------- memproj body ----------------
__device__ __forceinline__ void memproj_body(const float* __restrict__ A, const float* __restrict__ B,
                                             const float* __restrict__ bias, __half* __restrict__ C,
                                             int lb, int tid, char* buf)
{
    float (*Ast)[64] = (float(*)[64])buf;
    float (*Bs)[64]  = (float(*)[64])(buf + 4096);
    const int tx = tid & 15, ty = tid >> 4;
    const int bn = lb * 64;
    const int ar = tid >> 2, ak = (tid & 3) << 2;
    const int bk = tid >> 4, bc = (tid & 15) << 2;

    float acc[4][4];
    #pragma unroll
    for (int i = 0; i < 4; i++)
        #pragma unroll
        for (int j = 0; j < 4; j++) acc[i][j] = 0.f;

    for (int k0 = 0; k0 < CDIM; k0 += 16) {
        const float4 av = *(const float4*)(A + (size_t)ar * CDIM + k0 + ak);
        const float4 bv = *(const float4*)(B + (size_t)(k0 + bk) * CDIM + bn + bc);
        __syncthreads();
        Ast[ak + 0][ar] = av.x;
        Ast[ak + 1][ar] = av.y;
        Ast[ak + 2][ar] = av.z;
        Ast[ak + 3][ar] = av.w;
        *(float4*)&Bs[bk][bc] = bv;
        __syncthreads();
        #pragma unroll
        for (int kk = 0; kk < 16; kk++) {
            const float4 a = *(const float4*)&Ast[kk][ty * 4];
            const float4 b = *(const float4*)&Bs[kk][tx * 4];
            const float arr[4] = {a.x, a.y, a.z, a.w};
            const float brr[4] = {b.x, b.y, b.z, b.w};
            #pragma unroll
            for (int i = 0; i < 4; i++)
                #pragma unroll
                for (int j = 0; j < 4; j++)
                    acc[i][j] = fmaf(arr[i], brr[j], acc[i][j]);
        }
    }
    #pragma unroll
    for (int i = 0; i < 4; i++) {
        const int col = bn + tx * 4;
        const float4 bsv = *(const float4*)(bias + col);
        __half2* cp = (__half2*)(C + (size_t)(ty * 4 + i) * CDIM + col);
        cp[0] = __floats2half2_rn(acc[i][0] + bsv.x, acc[i][1] + bsv.y);
        cp[1] = __floats2half2_rn(acc[i][2] + bsv.z, acc[i][3] + bsv.w);
    }
}

// ---------------- fused prep ----------------
#define PREP_BLOCKS 16400

__global__ __launch_bounds__(256)
void prep_kernel(const float* __restrict__ w_qkv, const float* __restrict__ w_out,
                 const float* __restrict__ w_fc1, const float* __restrict__ w_fc2,
                 __half* __restrict__ WQKVT, __half* __restrict__ WOUTT,
                 __half* __restrict__ WFC1T, __half* __restrict__ WFC2T,
                 const float* __restrict__ x, const float* __restrict__ ln1_g,
                 const float* __restrict__ ln1_b, __half* __restrict__ H,
                 const float* __restrict__ memory, const float* __restrict__ w_mem,
                 const float* __restrict__ b_mem, __half* __restrict__ MEMP)
{
    __shared__ char buf[8448];
    const int bid = blockIdx.x;
    const int tid = threadIdx.x;

    if (bid < 3072) {
        transpose_body(w_qkv, WQKVT, CDIM, 3 * CDIM, bid, tid, buf);
    } else if (bid < 4096) {
        transpose_body(w_out, WOUTT, CDIM, CDIM, bid - 3072, tid, buf);
    } else if (bid < 8192) {
        transpose_body(w_fc1, WFC1T, CDIM, HIDDEN, bid - 4096, tid, buf);
    } else if (bid < 12288) {
        transpose_body(w_fc2, WFC2T, HIDDEN, CDIM, bid - 8192, tid, buf);
    } else if (bid < 16384) {
        ln_body(x, ln1_g, ln1_b, H, bid - 12288, tid, (float*)buf);
    } else {
        memproj_body(memory, w_mem, b_mem, MEMP, bid - 16384, tid, buf);
    }
}

// ---------------- fp16 mma GEMM: BK=64, 3-stage cp.async + ldmatrix ----------------
#define GPAD 72
#define GSTH (128 * GPAD)                 // halfs per stage per matrix
#define GSMEM_BYTES (3 * 2 * GSTH * 2)    // 110592

template<int EPI, typename TOut>
__global__ __launch_bounds__(256, 2)
void gemm_mma(const __half* __restrict__ A, const __half* __restrict__ Bt,
              const float* __restrict__ bias, const float* __restrict__ res,
              TOut* __restrict__ C, int M, int N, int K)
{
    extern __shared__ __half sgm[];
    const uint32_t sAa = smem_u32(sgm);
    const uint32_t sBa = sAa + 3u * GSTH * 2u;

    const int tid = threadIdx.x;
    const int wid = tid >> 5, lane = tid & 31;
    const int wm = (wid & 1) * 64;
    const int wn = (wid >> 1) * 32;
    const int bm = blockIdx.y * 128;
    const int bn = blockIdx.x * 128;

    // loaders: each thread loads one half-row (32 halfs = 4 cp16) of A and B per chunk
    const int lr  = tid >> 1;             // 0..127
    const int lc0 = (tid & 1) * 32;       // 0 or 32 halfs
    const __half* Ap = A  + (size_t)(bm + lr) * K + lc0;
    const __half* Bp = Bt + (size_t)(bn + lr) * K + lc0;
    const uint32_t soff = ((uint32_t)lr * GPAD + (uint32_t)lc0) * 2u;

    const int qr = lane >> 2;
    const int qc = lane & 3;
    const int nchunk = K / 64;

    const int arow = lane & 15;
    const int acol = (lane >> 4) * 8;
    const int brow = (lane & 7) + ((lane & 16) ? 8 : 0);
    const int bcol = ((lane >> 3) & 1) * 8;
    const uint32_t aoffb = ((uint32_t)(wm + arow) * GPAD + acol) * 2u;
    const uint32_t boffb = ((uint32_t)(wn + brow) * GPAD + bcol) * 2u;

    float acc[4][4][4];
    #pragma unroll
    for (int i = 0; i < 4; i++)
        #pragma unroll
        for (int j = 0; j < 4; j++)
            #pragma unroll
            for (int r = 0; r < 4; r++) acc[i][j][r] = 0.f;

    // prologue: chunks 0,1 into stages 0,1
    #pragma unroll
    for (int pc = 0; pc < 2; pc++) {
        const uint32_t sb = (uint32_t)pc * GSTH * 2u;
        const int k0 = pc * 64;
        #pragma unroll
        for (int p = 0; p < 4; p++) {
            cp16(sAa + sb + soff + p * 16u, Ap + k0 + p * 8);
            cp16(sBa + sb + soff + p * 16u, Bp + k0 + p * 8);
        }
        asm volatile("cp.async.commit_group;");
    }

    int sc = 0;
    for (int ch = 0; ch < nchunk; ch++) {
        asm volatile("cp.async.wait_group 1;");
        __syncthreads();

        if (ch + 2 < nchunk) {
            int sw = sc + 2; if (sw >= 3) sw -= 3;
            const uint32_t sb = (uint32_t)sw * GSTH * 2u;
            const int k0 = (ch + 2) * 64;
            #pragma unroll
            for (int p = 0; p < 4; p++) {
                cp16(sAa + sb + soff + p * 16u, Ap + k0 + p * 8);
                cp16(sBa + sb + soff + p * 16u, Bp + k0 + p * 8);
            }
        }
        asm volatile("cp.async.commit_group;");

        const uint32_t aB = sAa + (uint32_t)sc * GSTH * 2u + aoffb;
        const uint32_t bB = sBa + (uint32_t)sc * GSTH * 2u + boffb;

        #pragma unroll
        for (int ks = 0; ks < 4; ks++) {
            const uint32_t kb = ks * 32;
            uint32_t bb0[4], bb1[4];
            ldsm4(bb0, bB + kb);
            ldsm4(bb1, bB + 16u * GPAD * 2u + kb);
            #pragma unroll
            for (int mt = 0; mt < 4; mt++) {
                uint32_t a[4];
                ldsm4(a, aB + (uint32_t)mt * 16u * GPAD * 2u + kb);
                mma_f16(acc[mt][0], a[0], a[1], a[2], a[3], bb0[0], bb0[1]);
                mma_f16(acc[mt][1], a[0], a[1], a[2], a[3], bb0[2], bb0[3]);
                mma_f16(acc[mt][2], a[0], a[1], a[2], a[3], bb1[0], bb1[1]);
                mma_f16(acc[mt][3], a[0], a[1], a[2], a[3], bb1[2], bb1[3]);
            }
        }
        if (++sc == 3) sc = 0;
    }

    #pragma unroll
    for (int mt = 0; mt < 4; mt++) {
        #pragma unroll
        for (int half_ = 0; half_ < 2; half_++) {
            const int row = bm + wm + mt * 16 + qr + half_ * 8;
            const float* Rrow = res + (size_t)row * N;
            #pragma unroll
            for (int nt = 0; nt < 4; nt++) {
                const int col = bn + wn + nt * 8 + qc * 2;
                float v0 = acc[mt][nt][half_ * 2 + 0] + bias[col];
                float v1 = acc[mt][nt][half_ * 2 + 1] + bias[col + 1];
                if (EPI == 1) {
                    const float2 rv = *(const float2*)(Rrow + col);
                    v0 += rv.x; v1 += rv.y;
                }
                if (EPI == 2) {
                    v0 = 0.5f * v0 * (1.0f + erff(v0 * 0.70710678118654752f));
                    v1 = 0.5f * v1 * (1.0f + erff(v1 * 0.70710678118654752f));
                }
                TOut* Crow = C + (size_t)row * N;
                if (sizeof(TOut) == 2) {
                    *(__half2*)((__half*)Crow + col) = __floats2half2_rn(v0, v1);
                } else {
                    *(float2*)((float*)Crow + col) = make_float2(v0, v1);
                }
            }
        }
    }
}

// ---------------- fp16 mma attention (R9-proven, 2-stage) ----------------
#define QT   128
#define KC   64
#define DPH  72
#define ATTN_SMEM ((128*DPH + 2*64*DPH + 2*64*DPH + 128*DPH) * 2)   // 73728

__device__ __forceinline__ void issue_kv(uint32_t kDst, uint32_t vDst,
                                         const __half* __restrict__ kSrc,
                                         const __half* __restrict__ vSrc,
                                         size_t rstride, int tid)
{
    const int r = tid >> 2;
    const uint32_t off = (uint32_t)r * DPH * 2u + (uint32_t)(tid & 3) * 32u;
    const __half* ks = kSrc + (size_t)r * rstride + (tid & 3) * 16;
    const __half* vs = vSrc + (size_t)r * rstride + (tid & 3) * 16;
    cp16(kDst + off,       ks);
    cp16(kDst + off + 16u, ks + 8);
    cp16(vDst + off,       vs);
    cp16(vDst + off + 16u, vs + 8);
}

__device__ __forceinline__ void tile_mma_qk(uint32_t aAddr, uint32_t bAddr, float acc[8][4])
{
    #pragma unroll
    for (int ks = 0; ks < 4; ks++) {
        const uint32_t kb = ks * 32;
        uint32_t a[4];
        ldsm4(a, aAddr + kb);
        #pragma unroll
        for (int p = 0; p < 4; p++) {
            uint32_t bb[4];
            ldsm4(bb, bAddr + (uint32_t)p * 16u * DPH * 2u + kb);
            mma_f16(acc[2 * p],     a[0], a[1], a[2], a[3], bb[0], bb[1]);
            mma_f16(acc[2 * p + 1], a[0], a[1], a[2], a[3], bb[2], bb[3]);
        }
    }
}

__device__ __forceinline__ void tile_mma_pv(uint32_t aAddr, uint32_t bAddr, float acc[8][4])
{
    #pragma unroll
    for (int ks = 0; ks < 4; ks++) {
        const uint32_t kb = ks * 32;
        const uint32_t vb = (uint32_t)ks * 16u * DPH * 2u;
        uint32_t a[4];
        ldsm4(a, aAddr + kb);
        #pragma unroll
        for (int p = 0; p < 4; p++) {
            uint32_t bb[4];
            ldsm4t(bb, bAddr + vb + (uint32_t)p * 32u);
            mma_f16(acc[2 * p],     a[0], a[1], a[2], a[3], bb[0], bb[1]);
            mma_f16(acc[2 * p + 1], a[0], a[1], a[2], a[3], bb[2], bb[3]);
        }
    }
}

__global__ __launch_bounds__(256)
void attn_mma(const __half* __restrict__ qkv, const __half* __restrict__ memp,
              __half* __restrict__ out)
{
    extern __shared__ __half smh[];
    __half* Qsh = smh;
    __half* Kst = smh + 128 * DPH;
    __half* Vst = Kst + 2 * 64 * DPH;
    __half* Psh = Vst + 2 * 64 * DPH;

    const int tid  = threadIdx.x;
    const int wid  = tid >> 5, lane = tid & 31;
    const int qr   = lane >> 2, qc = lane & 3;
    const int m0   = wid * 16;
    const int h    = blockIdx.y, b = blockIdx.z;
    const int row0 = blockIdx.x * QT;

    const int arow = lane & 15;
    const int acol = (lane >> 4) * 8;
    const int brow = (lane & 7) + ((lane & 16) ? 8 : 0);
    const int bcol = ((lane >> 3) & 1) * 8;

    const uint32_t qAddr = smem_u32(Qsh) + ((uint32_t)(m0 + arow) * DPH + acol) * 2u;
    const uint32_t pAddr = smem_u32(Psh) + ((uint32_t)(m0 + arow) * DPH + acol) * 2u;
    const uint32_t kBase = smem_u32(Kst);
    const uint32_t vBase = smem_u32(Vst);
    const uint32_t kFragOff = ((uint32_t)brow * DPH + bcol) * 2u;
    const uint32_t vFragOff = ((uint32_t)arow * DPH + acol) * 2u;
    const uint32_t stageB = 64u * DPH * 2u;

    const __half* kSrc0 = qkv + ((size_t)(b * TSEQ)) * (3 * CDIM) + CDIM + h * 64;
    const __half* vSrc0 = qkv + ((size_t)(b * TSEQ)) * (3 * CDIM) + 2 * CDIM + h * 64;

    {
        const int r  = tid >> 1;
        const int c0 = (tid & 1) * 32;
        const __half2 sc = __float2half2_rn(0.125f);
        const __half2* qp = (const __half2*)(qkv + ((size_t)(b * TSEQ + row0 + r)) * (3 * CDIM) + h * 64 + c0);
        __half2* qd = (__half2*)&Qsh[r * DPH + c0];
        #pragma unroll
        for (int j = 0; j < 16; j++)
            qd[j] = __hmul2(qp[j], sc);
    }

    issue_kv(kBase, vBase, kSrc0, vSrc0, 3 * CDIM, tid);
    asm volatile("cp.async.commit_group;");

    float mM[2] = {-1e30f, -1e30f};
    float lL[2] = {0.f, 0.f};
    float oacc[8][4];
    #pragma unroll
    for (int nt = 0; nt < 8; nt++)
        #pragma unroll
        for (int r = 0; r < 4; r++) oacc[nt][r] = 0.f;

    const int NCH = TSEQ / KC;
    for (int ci = 0; ci < NCH; ci++) {
        asm volatile("cp.async.wait_group 0;");
        __syncthreads();

        if (ci + 1 < NCH) {
            const int sn = (ci + 1) & 1;
            issue_kv(kBase + (uint32_t)sn * stageB, vBase + (uint32_t)sn * stageB,
                     kSrc0 + (size_t)(ci + 1) * KC * (3 * CDIM),
                     vSrc0 + (size_t)(ci + 1) * KC * (3 * CDIM),
                     3 * CDIM, tid);
        }
        asm volatile("cp.async.commit_group;");

        const int st = ci & 1;
        const uint32_t kAddr = kBase + (uint32_t)st * stageB + kFragOff;
        const uint32_t vAddr = vBase + (uint32_t)st * stageB + vFragOff;

        float sacc[8][4];
        #pragma unroll
        for (int nt = 0; nt < 8; nt++)
            #pragma unroll
            for (int r = 0; r < 4; r++) sacc[nt][r] = 0.f;
        tile_mma_qk(qAddr, kAddr, sacc);

        float mx0 = -1e30f, mx1 = -1e30f;
        #pragma unroll
        for (int nt = 0; nt < 8; nt++) {
            mx0 = fmaxf(mx0, fmaxf(sacc[nt][0], sacc[nt][1]));
            mx1 = fmaxf(mx1, fmaxf(sacc[nt][2], sacc[nt][3]));
        }
        #pragma unroll
        for (int off = 1; off < 4; off <<= 1) {
            mx0 = fmaxf(mx0, __shfl_xor_sync(0xffffffffu, mx0, off));
            mx1 = fmaxf(mx1, __shfl_xor_sync(0xffffffffu, mx1, off));
        }
        const float mn0 = fmaxf(mM[0], mx0);
        const float mn1 = fmaxf(mM[1], mx1);
        const float f0 = __expf(mM[0] - mn0);
        const float f1 = __expf(mM[1] - mn1);
        mM[0] = mn0; mM[1] = mn1;

        float rs0 = 0.f, rs1 = 0.f;
        #pragma unroll
        for (int nt = 0; nt < 8; nt++) {
            const __half2 p01 = __floats2half2_rn(__expf(sacc[nt][0] - mn0),
                                                  __expf(sacc[nt][1] - mn0));
            const __half2 p23 = __floats2half2_rn(__expf(sacc[nt][2] - mn1),
                                                  __expf(sacc[nt][3] - mn1));
            *(__half2*)&Psh[(m0 + qr)     * DPH + nt * 8 + 2 * qc] = p01;
            *(__half2*)&Psh[(m0 + qr + 8) * DPH + nt * 8 + 2 * qc] = p23;
            const float2 f01 = __half22float2(p01);
            const float2 f23 = __half22float2(p23);
            rs0 += f01.x + f01.y; rs1 += f23.x + f23.y;
        }
        #pragma unroll
        for (int off = 1; off < 4; off <<= 1) {
            rs0 += __shfl_xor_sync(0xffffffffu, rs0, off);
            rs1 += __shfl_xor_sync(0xffffffffu, rs1, off);
        }
        lL[0] = lL[0] * f0 + rs0;
        lL[1] = lL[1] * f1 + rs1;
        #pragma unroll
        for (int nt = 0; nt < 8; nt++) {
            oacc[nt][0] *= f0; oacc[nt][1] *= f0;
            oacc[nt][2] *= f1; oacc[nt][3] *= f1;
        }
        __syncwarp();

        tile_mma_pv(pAddr, vAddr, oacc);
    }

    // ---- compressive memory attention ----
    __syncthreads();
    issue_kv(kBase, vBase, memp + h * 64, memp + h * 64, CDIM, tid);
    asm volatile("cp.async.commit_group;");
    asm volatile("cp.async.wait_group 0;");
    __syncthreads();

    float sacc[8][4];
    #pragma unroll
    for (int nt = 0; nt < 8; nt++)
        #pragma unroll
        for (int r = 0; r < 4; r++) sacc[nt][r] = 0.f;
    tile_mma_qk(qAddr, kBase + kFragOff, sacc);

    float mx0 = -1e30f, mx1 = -1e30f;
    #pragma unroll
    for (int nt = 0; nt < 8; nt++) {
        mx0 = fmaxf(mx0, fmaxf(sacc[nt][0], sacc[nt][1]));
        mx1 = fmaxf(mx1, fmaxf(sacc[nt][2], sacc[nt][3]));
    }
    #pragma unroll
    for (int off = 1; off < 4; off <<= 1) {
        mx0 = fmaxf(mx0, __shfl_xor_sync(0xffffffffu, mx0, off));
        mx1 = fmaxf(mx1, __shfl_xor_sync(0xffffffffu, mx1, off));
    }
    float rs0 = 0.f, rs1 = 0.f;
    #pragma unroll
    for (int nt = 0; nt < 8; nt++) {
        const __half2 p01 = __floats2half2_rn(__expf(sacc[nt][0] - mx0),
                                              __expf(sacc[nt][1] - mx0));
        const __half2 p23 = __floats2half2_rn(__expf(sacc[nt][2] - mx1),
                                              __expf(sacc[nt][3] - mx1));
        *(__half2*)&Psh[(m0 + qr)     * DPH + nt * 8 + 2 * qc] = p01;
        *(__half2*)&Psh[(m0 + qr + 8) * DPH + nt * 8 + 2 * qc] = p23;
        const float2 f01 = __half22float2(p01);
        const float2 f23 = __half22float2(p23);
        rs0 += f01.x + f01.y; rs1 += f23.x + f23.y;
    }
    #pragma unroll
    for (int off = 1; off < 4; off <<= 1) {
        rs0 += __shfl_xor_sync(0xffffffffu, rs0, off);
        rs1 += __shfl_xor_sync(0xffffffffu, rs1, off);
    }
    __syncwarp();

    float oacc2[8][4];
    #pragma unroll
    for (int nt = 0; nt < 8; nt++)
        #pragma unroll
        for (int r = 0; r < 4; r++) oacc2[nt][r] = 0.f;
    tile_mma_pv(pAddr, vBase + vFragOff, oacc2);

    const float i0 = 1.f / lL[0], i1 = 1.f / lL[1];
    const float j0 = 1.f / rs0,   j1 = 1.f / rs1;
    #pragma unroll
    for (int nt = 0; nt < 8; nt++) {
        const int col = h * 64 + nt * 8 + 2 * qc;
        const int r0 = b * TSEQ + row0 + m0 + qr;
        *(__half2*)(out + (size_t)r0 * CDIM + col) =
            __floats2half2_rn(oacc[nt][0] * i0 + oacc2[nt][0] * j0,
                              oacc[nt][1] * i0 + oacc2[nt][1] * j0);
        *(__half2*)(out + (size_t)(r0 + 8) * CDIM + col) =
            __floats2half2_rn(oacc[nt][2] * i1 + oacc2[nt][2] * j1,
                              oacc[nt][3] * i1 + oacc2[nt][3] * j1);
    }
}

// ---------------- launch ----------------
extern "C" void kernel_launch(void* const* d_in, const int* in_sizes, int n_in,
                              void* d_out, int out_size)
{
    const float* x      = (const float*)d_in[0];
    const float* memory = (const float*)d_in[1];
    const float* ln1_g  = (const float*)d_in[2];
    const float* ln1_b  = (const float*)d_in[3];
    const float* w_qkv  = (const float*)d_in[4];
    const float* b_qkv  = (const float*)d_in[5];
    const float* w_out  = (const float*)d_in[6];
    const float* b_out  = (const float*)d_in[7];
    const float* w_mem  = (const float*)d_in[8];
    const float* b_mem  = (const float*)d_in[9];
    const float* ln2_g  = (const float*)d_in[10];
    const float* ln2_b  = (const float*)d_in[11];
    const float* w_fc1  = (const float*)d_in[12];
    const float* b_fc1  = (const float*)d_in[13];
    const float* w_fc2  = (const float*)d_in[14];
    const float* b_fc2  = (const float*)d_in[15];
    float* out = (float*)d_out;

    __half *pH, *pQKV, *pMEMP, *pATTN, *pH2, *pHID;
    __half *pWQKVT, *pWOUTT, *pWFC1T, *pWFC2T;
    float *pX1;
    cudaGetSymbolAddress((void**)&pH,     g_H);
    cudaGetSymbolAddress((void**)&pQKV,   g_QKV);
    cudaGetSymbolAddress((void**)&pMEMP,  g_MEMP);
    cudaGetSymbolAddress((void**)&pATTN,  g_ATTN);
    cudaGetSymbolAddress((void**)&pX1,    g_X1);
    cudaGetSymbolAddress((void**)&pH2,    g_H2);
    cudaGetSymbolAddress((void**)&pHID,   g_HID);
    cudaGetSymbolAddress((void**)&pWQKVT, g_WQKVT);
    cudaGetSymbolAddress((void**)&pWOUTT, g_WOUTT);
    cudaGetSymbolAddress((void**)&pWFC1T, g_WFC1T);
    cudaGetSymbolAddress((void**)&pWFC2T, g_WFC2T);

    cudaFuncSetAttribute(attn_mma, cudaFuncAttributeMaxDynamicSharedMemorySize, ATTN_SMEM);
    cudaFuncSetAttribute(gemm_mma<0, __half>, cudaFuncAttributeMaxDynamicSharedMemorySize, GSMEM_BYTES);
    cudaFuncSetAttribute(gemm_mma<1, float>,  cudaFuncAttributeMaxDynamicSharedMemorySize, GSMEM_BYTES);
    cudaFuncSetAttribute(gemm_mma<2, __half>, cudaFuncAttributeMaxDynamicSharedMemorySize, GSMEM_BYTES);

    const int ROWS = BATCH * TSEQ;  // 4096

    prep_kernel<<<PREP_BLOCKS, 256>>>(w_qkv, w_out, w_fc1, w_fc2,
                                      pWQKVT, pWOUTT, pWFC1T, pWFC2T,
                                      x, ln1_g, ln1_b, pH,
                                      memory, w_mem, b_mem, pMEMP);

    gemm_mma<0, __half><<<dim3(3 * CDIM / 128, ROWS / 128), 256, GSMEM_BYTES>>>(
        pH, pWQKVT, b_qkv, nullptr, pQKV, ROWS, 3 * CDIM, CDIM);

    attn_mma<<<dim3(TSEQ / QT, NHEAD, BATCH), 256, ATTN_SMEM>>>(pQKV, pMEMP, pATTN);

    gemm_mma<1, float><<<dim3(CDIM / 128, ROWS / 128), 256, GSMEM_BYTES>>>(
        pATTN, pWOUTT, b_out, x, pX1, ROWS, CDIM, CDIM);

    ln_kernel<<<ROWS, 256>>>(pX1, ln2_g, ln2_b, pH2);

    gemm_mma<2, __half><<<dim3(HIDDEN / 128, ROWS / 128), 256, GSMEM_BYTES>>>(
        pH2, pWFC1T, b_fc1, nullptr, pHID, ROWS, HIDDEN, CDIM);

    gemm_mma<1, float><<<dim3(CDIM / 128, ROWS / 128), 256, GSMEM_BYTES>>>(
        pHID, pWFC2T, b_fc2, pX1, out, ROWS, CDIM, HIDDEN);
}

// round 14
// speedup vs baseline: 1.1447x; 1.1447x over previous
#include <cuda_runtime.h>
#include <cuda_fp16.h>
#include <math.h>
#include <stdint.h>

#define CDIM   1024
#define TSEQ   2048
#define BATCH  2
#define NHEAD  16
#define HDIM   64
#define MMEM   64
#define HIDDEN 4096

// ---------------- scratch (device globals; no allocation) ----------------
__device__ __half g_H    [BATCH*TSEQ*CDIM];
__device__ __half g_QKV  [BATCH*TSEQ*3*CDIM];
__device__ __half g_MEMP [MMEM*CDIM];
__device__ __half g_ATTN [BATCH*TSEQ*CDIM];
__device__ float  g_X1   [BATCH*TSEQ*CDIM];
__device__ __half g_H2   [BATCH*TSEQ*CDIM];
__device__ __half g_HID  [BATCH*TSEQ*HIDDEN];
__device__ __half g_WQKVT[3*CDIM*CDIM];
__device__ __half g_WOUTT[CDIM*CDIM];
__device__ __half g_WFC1T[HIDDEN*CDIM];
__device__ __half g_WFC2T[CDIM*HIDDEN];

__device__ __forceinline__ uint32_t smem_u32(const void* p) {
    uint32_t a;
    asm("{ .reg .u64 t; cvta.to.shared.u64 t, %1; cvt.u32.u64 %0, t; }" : "=r"(a) : "l"(p));
    return a;
}
__device__ __forceinline__ void cp16(uint32_t dst, const void* src) {
    asm volatile("cp.async.cg.shared.global [%0], [%1], 16;" :: "r"(dst), "l"(src));
}
__device__ __forceinline__ void mma_f16(float* c, uint32_t a0, uint32_t a1,
                                        uint32_t a2, uint32_t a3,
                                        uint32_t b0, uint32_t b1)
{
    asm volatile(
        "mma.sync.aligned.m16n8k16.row.col.f32.f16.f16.f32 "
        "{%0,%1,%2,%3}, {%4,%5,%6,%7}, {%8,%9}, {%0,%1,%2,%3};"
        : "+f"(c[0]), "+f"(c[1]), "+f"(c[2]), "+f"(c[3])
        : "r"(a0), "r"(a1), "r"(a2), "r"(a3), "r"(b0), "r"(b1));
}
__device__ __forceinline__ void ldsm4(uint32_t* r, uint32_t addr) {
    asm volatile("ldmatrix.sync.aligned.m8n8.x4.shared.b16 {%0,%1,%2,%3}, [%4];"
        : "=r"(r[0]), "=r"(r[1]), "=r"(r[2]), "=r"(r[3]) : "r"(addr));
}
__device__ __forceinline__ void ldsm4t(uint32_t* r, uint32_t addr) {
    asm volatile("ldmatrix.sync.aligned.m8n8.x4.trans.shared.b16 {%0,%1,%2,%3}, [%4];"
        : "=r"(r[0]), "=r"(r[1]), "=r"(r[2]), "=r"(r[3]) : "r"(addr));
}

// ---------------- LayerNorm body ----------------
__device__ __forceinline__ void ln_body(const float* __restrict__ x, const float* __restrict__ g,
                                        const float* __restrict__ b, __half* __restrict__ y,
                                        int row, int tid, float* red)
{
    const float4 v = ((const float4*)(x + (size_t)row * CDIM))[tid];
    float s  = v.x + v.y + v.z + v.w;
    float ss = v.x*v.x + v.y*v.y + v.z*v.z + v.w*v.w;
    #pragma unroll
    for (int off = 16; off; off >>= 1) {
        s  += __shfl_xor_sync(0xffffffffu, s,  off);
        ss += __shfl_xor_sync(0xffffffffu, ss, off);
    }
    if ((tid & 31) == 0) { red[tid >> 5] = s; red[8 + (tid >> 5)] = ss; }
    __syncthreads();
    if (tid == 0) {
        float ts = 0.f, tss = 0.f;
        #pragma unroll
        for (int w = 0; w < 8; w++) { ts += red[w]; tss += red[8 + w]; }
        red[16] = ts; red[17] = tss;
    }
    __syncthreads();
    const float mu  = red[16] * (1.f / CDIM);
    const float var = red[17] * (1.f / CDIM) - mu * mu;
    const float inv = rsqrtf(var + 1e-5f);
    const float4 gv = ((const float4*)g)[tid];
    const float4 bv = ((const float4*)b)[tid];
    __half2 h01 = __floats2half2_rn((v.x - mu) * inv * gv.x + bv.x,
                                    (v.y - mu) * inv * gv.y + bv.y);
    __half2 h23 = __floats2half2_rn((v.z - mu) * inv * gv.z + bv.z,
                                    (v.w - mu) * inv * gv.w + bv.w);
    __half2* yp = (__half2*)(y + (size_t)row * CDIM + tid * 4);
    yp[0] = h01; yp[1] = h23;
}

__global__ __launch_bounds__(256)
void ln_kernel(const float* __restrict__ x, const float* __restrict__ g,
               const float* __restrict__ b, __half* __restrict__ y)
{
    __shared__ float red[18];
    ln_body(x, g, b, y, blockIdx.x, threadIdx.x, red);
}

// ---------------- transpose body ----------------
__device__ __forceinline__ void transpose_body(const float* __restrict__ S, __half* __restrict__ D,
                                               int K, int N, int lb, int tid, char* buf)
{
    float (*t)[33] = (float(*)[33])buf;
    const int gx = N / 32;
    const int bx = (lb % gx) * 32;
    const int by = (lb / gx) * 32;
    const int x = tid & 31, y = tid >> 5;
    #pragma unroll
    for (int i = 0; i < 32; i += 8)
        t[y + i][x] = S[(size_t)(by + y + i) * N + bx + x];
    __syncthreads();
    #pragma unroll
    for (int i = 0; i < 32; i += 8)
        D[(size_t)(bx + y + i) * K + by + x] = __float2half_rn(t[x][y + i]);
}

// ---------------- memproj body ----------------
__device__ __forceinline__ void memproj_body(const float* __restrict__ A, const float* __restrict__ B,
                                             const float* __restrict__ bias, __half* __restrict__ C,
                                             int lb, int tid, char* buf)
{
    float (*Ast)[64] = (float(*)[64])buf;
    float (*Bs)[64]  = (float(*)[64])(buf + 4096);
    const int tx = tid & 15, ty = tid >> 4;
    const int bn = lb * 64;
    const int ar = tid >> 2, ak = (tid & 3) << 2;
    const int bk = tid >> 4, bc = (tid & 15) << 2;

    float acc[4][4];
    #pragma unroll
    for (int i = 0; i < 4; i++)
        #pragma unroll
        for (int j = 0; j < 4; j++) acc[i][j] = 0.f;

    for (int k0 = 0; k0 < CDIM; k0 += 16) {
        const float4 av = *(const float4*)(A + (size_t)ar * CDIM + k0 + ak);
        const float4 bv = *(const float4*)(B + (size_t)(k0 + bk) * CDIM + bn + bc);
        __syncthreads();
        Ast[ak + 0][ar] = av.x;
        Ast[ak + 1][ar] = av.y;
        Ast[ak + 2][ar] = av.z;
        Ast[ak + 3][ar] = av.w;
        *(float4*)&Bs[bk][bc] = bv;
        __syncthreads();
        #pragma unroll
        for (int kk = 0; kk < 16; kk++) {
            const float4 a = *(const float4*)&Ast[kk][ty * 4];
            const float4 b = *(const float4*)&Bs[kk][tx * 4];
            const float arr[4] = {a.x, a.y, a.z, a.w};
            const float brr[4] = {b.x, b.y, b.z, b.w};
            #pragma unroll
            for (int i = 0; i < 4; i++)
                #pragma unroll
                for (int j = 0; j < 4; j++)
                    acc[i][j] = fmaf(arr[i], brr[j], acc[i][j]);
        }
    }
    #pragma unroll
    for (int i = 0; i < 4; i++) {
        const int col = bn + tx * 4;
        const float4 bsv = *(const float4*)(bias + col);
        __half2* cp = (__half2*)(C + (size_t)(ty * 4 + i) * CDIM + col);
        cp[0] = __floats2half2_rn(acc[i][0] + bsv.x, acc[i][1] + bsv.y);
        cp[1] = __floats2half2_rn(acc[i][2] + bsv.z, acc[i][3] + bsv.w);
    }
}

// ---------------- fused prep ----------------
#define PREP_BLOCKS 16400

__global__ __launch_bounds__(256)
void prep_kernel(const float* __restrict__ w_qkv, const float* __restrict__ w_out,
                 const float* __restrict__ w_fc1, const float* __restrict__ w_fc2,
                 __half* __restrict__ WQKVT, __half* __restrict__ WOUTT,
                 __half* __restrict__ WFC1T, __half* __restrict__ WFC2T,
                 const float* __restrict__ x, const float* __restrict__ ln1_g,
                 const float* __restrict__ ln1_b, __half* __restrict__ H,
                 const float* __restrict__ memory, const float* __restrict__ w_mem,
                 const float* __restrict__ b_mem, __half* __restrict__ MEMP)
{
    __shared__ char buf[8448];
    const int bid = blockIdx.x;
    const int tid = threadIdx.x;

    if (bid < 3072) {
        transpose_body(w_qkv, WQKVT, CDIM, 3 * CDIM, bid, tid, buf);
    } else if (bid < 4096) {
        transpose_body(w_out, WOUTT, CDIM, CDIM, bid - 3072, tid, buf);
    } else if (bid < 8192) {
        transpose_body(w_fc1, WFC1T, CDIM, HIDDEN, bid - 4096, tid, buf);
    } else if (bid < 12288) {
        transpose_body(w_fc2, WFC2T, HIDDEN, CDIM, bid - 8192, tid, buf);
    } else if (bid < 16384) {
        ln_body(x, ln1_g, ln1_b, H, bid - 12288, tid, (float*)buf);
    } else {
        memproj_body(memory, w_mem, b_mem, MEMP, bid - 16384, tid, buf);
    }
}

// ---------------- fp16 mma GEMM: BK=32, 4 stages, pair-processed (1 sync / 2 chunks) ----------------
#define SKEWH 40
#define GST   (128 * SKEWH)                 // halfs per stage per matrix
#define GSMEM_BYTES (4 * 2 * GST * 2)       // 81920

template<int EPI, typename TOut>
__global__ __launch_bounds__(256, 2)
void gemm_mma(const __half* __restrict__ A, const __half* __restrict__ Bt,
              const float* __restrict__ bias, const float* __restrict__ res,
              TOut* __restrict__ C, int M, int N, int K)
{
    extern __shared__ __half sgm[];
    const uint32_t sAa = smem_u32(sgm);
    const uint32_t sBa = sAa + 4u * GST * 2u;

    const int tid = threadIdx.x;
    const int wid = tid >> 5, lane = tid & 31;
    const int wm = (wid & 1) * 64;
    const int wn = (wid >> 1) * 32;
    const int bm = blockIdx.y * 128;
    const int bn = blockIdx.x * 128;

    // loader mapping identical to R12 (proven)
    const int lrow = tid >> 2;
    const int lcol = (tid & 3) << 3;
    const __half* Ap = A  + (size_t)(bm + lrow) * K + lcol;
    const __half* Bp = Bt + (size_t)(bn + lrow) * K + lcol;
    const uint32_t soff = ((uint32_t)lrow * SKEWH + (uint32_t)lcol) * 2u;

    const int qr = lane >> 2;
    const int qc = lane & 3;
    const int npairs = K / 64;              // chunks = K/32, pairs = chunks/2

    const int arow = lane & 15;
    const int acol = (lane >> 4) * 8;
    const int brow = (lane & 7) + ((lane & 16) ? 8 : 0);
    const int bcol = ((lane >> 3) & 1) * 8;
    const uint32_t aoffb = ((uint32_t)(wm + arow) * SKEWH + acol) * 2u;
    const uint32_t boffb = ((uint32_t)(wn + brow) * SKEWH + bcol) * 2u;

    float acc[4][4][4];
    #pragma unroll
    for (int i = 0; i < 4; i++)
        #pragma unroll
        for (int j = 0; j < 4; j++)
            #pragma unroll
            for (int r = 0; r < 4; r++) acc[i][j][r] = 0.f;

    // prologue: pair 0 (chunks 0,1 -> stages 0,1), one commit group
    #pragma unroll
    for (int pc = 0; pc < 2; pc++) {
        const uint32_t sb = (uint32_t)pc * GST * 2u;
        #pragma unroll
        for (int p = 0; p < 2; p++) {
            cp16(sAa + sb + soff + p * 64 * SKEWH * 2, Ap + (size_t)(p * 64) * K + pc * 32);
            cp16(sBa + sb + soff + p * 64 * SKEWH * 2, Bp + (size_t)(p * 64) * K + pc * 32);
        }
    }
    asm volatile("cp.async.commit_group;");

    for (int pr = 0; pr < npairs; pr++) {
        asm volatile("cp.async.wait_group 0;");
        __syncthreads();   // pair pr visible; all warps past pair pr-1 -> its stages free

        if (pr + 1 < npairs) {
            #pragma unroll
            for (int pc = 0; pc < 2; pc++) {
                const int ch = 2 * (pr + 1) + pc;           // next pair's chunks
                const uint32_t sb = (uint32_t)(ch & 3) * GST * 2u;
                const int k0 = ch * 32;
                #pragma unroll
                for (int p = 0; p < 2; p++) {
                    cp16(sAa + sb + soff + p * 64 * SKEWH * 2, Ap + (size_t)(p * 64) * K + k0);
                    cp16(sBa + sb + soff + p * 64 * SKEWH * 2, Bp + (size_t)(p * 64) * K + k0);
                }
            }
        }
        asm volatile("cp.async.commit_group;");

        // compute the pair's two chunks (stages (2*pr)&3, (2*pr+1)&3)
        #pragma unroll
        for (int pc = 0; pc < 2; pc++) {
            const int st = (2 * pr + pc) & 3;
            const uint32_t aB = sAa + (uint32_t)st * GST * 2u + aoffb;
            const uint32_t bB = sBa + (uint32_t)st * GST * 2u + boffb;

            #pragma unroll
            for (int ks = 0; ks < 2; ks++) {
                const uint32_t kb = ks * 32;
                uint32_t bb0[4], bb1[4];
                ldsm4(bb0, bB + kb);
                ldsm4(bb1, bB + 16u * SKEWH * 2u + kb);
                #pragma unroll
                for (int mt = 0; mt < 4; mt++) {
                    uint32_t a[4];
                    ldsm4(a, aB + (uint32_t)mt * 16u * SKEWH * 2u + kb);
                    mma_f16(acc[mt][0], a[0], a[1], a[2], a[3], bb0[0], bb0[1]);
                    mma_f16(acc[mt][1], a[0], a[1], a[2], a[3], bb0[2], bb0[3]);
                    mma_f16(acc[mt][2], a[0], a[1], a[2], a[3], bb1[0], bb1[1]);
                    mma_f16(acc[mt][3], a[0], a[1], a[2], a[3], bb1[2], bb1[3]);
                }
            }
        }
    }

    #pragma unroll
    for (int mt = 0; mt < 4; mt++) {
        #pragma unroll
        for (int half_ = 0; half_ < 2; half_++) {
            const int row = bm + wm + mt * 16 + qr + half_ * 8;
            const float* Rrow = res + (size_t)row * N;
            #pragma unroll
            for (int nt = 0; nt < 4; nt++) {
                const int col = bn + wn + nt * 8 + qc * 2;
                float v0 = acc[mt][nt][half_ * 2 + 0] + bias[col];
                float v1 = acc[mt][nt][half_ * 2 + 1] + bias[col + 1];
                if (EPI == 1) {
                    const float2 rv = *(const float2*)(Rrow + col);
                    v0 += rv.x; v1 += rv.y;
                }
                if (EPI == 2) {
                    v0 = 0.5f * v0 * (1.0f + erff(v0 * 0.70710678118654752f));
                    v1 = 0.5f * v1 * (1.0f + erff(v1 * 0.70710678118654752f));
                }
                TOut* Crow = C + (size_t)row * N;
                if (sizeof(TOut) == 2) {
                    *(__half2*)((__half*)Crow + col) = __floats2half2_rn(v0, v1);
                } else {
                    *(float2*)((float*)Crow + col) = make_float2(v0, v1);
                }
            }
        }
    }
}

// ---------------- fp16 mma attention (R9/R12-proven, 2-stage) ----------------
#define QT   128
#define KC   64
#define DPH  72
#define ATTN_SMEM ((128*DPH + 2*64*DPH + 2*64*DPH + 128*DPH) * 2)   // 73728

__device__ __forceinline__ void issue_kv(uint32_t kDst, uint32_t vDst,
                                         const __half* __restrict__ kSrc,
                                         const __half* __restrict__ vSrc,
                                         size_t rstride, int tid)
{
    const int r = tid >> 2;
    const uint32_t off = (uint32_t)r * DPH * 2u + (uint32_t)(tid & 3) * 32u;
    const __half* ks = kSrc + (size_t)r * rstride + (tid & 3) * 16;
    const __half* vs = vSrc + (size_t)r * rstride + (tid & 3) * 16;
    cp16(kDst + off,       ks);
    cp16(kDst + off + 16u, ks + 8);
    cp16(vDst + off,       vs);
    cp16(vDst + off + 16u, vs + 8);
}

__device__ __forceinline__ void tile_mma_qk(uint32_t aAddr, uint32_t bAddr, float acc[8][4])
{
    #pragma unroll
    for (int ks = 0; ks < 4; ks++) {
        const uint32_t kb = ks * 32;
        uint32_t a[4];
        ldsm4(a, aAddr + kb);
        #pragma unroll
        for (int p = 0; p < 4; p++) {
            uint32_t bb[4];
            ldsm4(bb, bAddr + (uint32_t)p * 16u * DPH * 2u + kb);
            mma_f16(acc[2 * p],     a[0], a[1], a[2], a[3], bb[0], bb[1]);
            mma_f16(acc[2 * p + 1], a[0], a[1], a[2], a[3], bb[2], bb[3]);
        }
    }
}

__device__ __forceinline__ void tile_mma_pv(uint32_t aAddr, uint32_t bAddr, float acc[8][4])
{
    #pragma unroll
    for (int ks = 0; ks < 4; ks++) {
        const uint32_t kb = ks * 32;
        const uint32_t vb = (uint32_t)ks * 16u * DPH * 2u;
        uint32_t a[4];
        ldsm4(a, aAddr + kb);
        #pragma unroll
        for (int p = 0; p < 4; p++) {
            uint32_t bb[4];
            ldsm4t(bb, bAddr + vb + (uint32_t)p * 32u);
            mma_f16(acc[2 * p],     a[0], a[1], a[2], a[3], bb[0], bb[1]);
            mma_f16(acc[2 * p + 1], a[0], a[1], a[2], a[3], bb[2], bb[3]);
        }
    }
}

__global__ __launch_bounds__(256)
void attn_mma(const __half* __restrict__ qkv, const __half* __restrict__ memp,
              __half* __restrict__ out)
{
    extern __shared__ __half smh[];
    __half* Qsh = smh;
    __half* Kst = smh + 128 * DPH;
    __half* Vst = Kst + 2 * 64 * DPH;
    __half* Psh = Vst + 2 * 64 * DPH;

    const int tid  = threadIdx.x;
    const int wid  = tid >> 5, lane = tid & 31;
    const int qr   = lane >> 2, qc = lane & 3;
    const int m0   = wid * 16;
    const int h    = blockIdx.y, b = blockIdx.z;
    const int row0 = blockIdx.x * QT;

    const int arow = lane & 15;
    const int acol = (lane >> 4) * 8;
    const int brow = (lane & 7) + ((lane & 16) ? 8 : 0);
    const int bcol = ((lane >> 3) & 1) * 8;

    const uint32_t qAddr = smem_u32(Qsh) + ((uint32_t)(m0 + arow) * DPH + acol) * 2u;
    const uint32_t pAddr = smem_u32(Psh) + ((uint32_t)(m0 + arow) * DPH + acol) * 2u;
    const uint32_t kBase = smem_u32(Kst);
    const uint32_t vBase = smem_u32(Vst);
    const uint32_t kFragOff = ((uint32_t)brow * DPH + bcol) * 2u;
    const uint32_t vFragOff = ((uint32_t)arow * DPH + acol) * 2u;
    const uint32_t stageB = 64u * DPH * 2u;

    const __half* kSrc0 = qkv + ((size_t)(b * TSEQ)) * (3 * CDIM) + CDIM + h * 64;
    const __half* vSrc0 = qkv + ((size_t)(b * TSEQ)) * (3 * CDIM) + 2 * CDIM + h * 64;

    {
        const int r  = tid >> 1;
        const int c0 = (tid & 1) * 32;
        const __half2 sc = __float2half2_rn(0.125f);
        const __half2* qp = (const __half2*)(qkv + ((size_t)(b * TSEQ + row0 + r)) * (3 * CDIM) + h * 64 + c0);
        __half2* qd = (__half2*)&Qsh[r * DPH + c0];
        #pragma unroll
        for (int j = 0; j < 16; j++)
            qd[j] = __hmul2(qp[j], sc);
    }

    issue_kv(kBase, vBase, kSrc0, vSrc0, 3 * CDIM, tid);
    asm volatile("cp.async.commit_group;");

    float mM[2] = {-1e30f, -1e30f};
    float lL[2] = {0.f, 0.f};
    float oacc[8][4];
    #pragma unroll
    for (int nt = 0; nt < 8; nt++)
        #pragma unroll
        for (int r = 0; r < 4; r++) oacc[nt][r] = 0.f;

    const int NCH = TSEQ / KC;
    for (int ci = 0; ci < NCH; ci++) {
        asm volatile("cp.async.wait_group 0;");
        __syncthreads();

        if (ci + 1 < NCH) {
            const int sn = (ci + 1) & 1;
            issue_kv(kBase + (uint32_t)sn * stageB, vBase + (uint32_t)sn * stageB,
                     kSrc0 + (size_t)(ci + 1) * KC * (3 * CDIM),
                     vSrc0 + (size_t)(ci + 1) * KC * (3 * CDIM),
                     3 * CDIM, tid);
        }
        asm volatile("cp.async.commit_group;");

        const int st = ci & 1;
        const uint32_t kAddr = kBase + (uint32_t)st * stageB + kFragOff;
        const uint32_t vAddr = vBase + (uint32_t)st * stageB + vFragOff;

        float sacc[8][4];
        #pragma unroll
        for (int nt = 0; nt < 8; nt++)
            #pragma unroll
            for (int r = 0; r < 4; r++) sacc[nt][r] = 0.f;
        tile_mma_qk(qAddr, kAddr, sacc);

        float mx0 = -1e30f, mx1 = -1e30f;
        #pragma unroll
        for (int nt = 0; nt < 8; nt++) {
            mx0 = fmaxf(mx0, fmaxf(sacc[nt][0], sacc[nt][1]));
            mx1 = fmaxf(mx1, fmaxf(sacc[nt][2], sacc[nt][3]));
        }
        #pragma unroll
        for (int off = 1; off < 4; off <<= 1) {
            mx0 = fmaxf(mx0, __shfl_xor_sync(0xffffffffu, mx0, off));
            mx1 = fmaxf(mx1, __shfl_xor_sync(0xffffffffu, mx1, off));
        }
        const float mn0 = fmaxf(mM[0], mx0);
        const float mn1 = fmaxf(mM[1], mx1);
        const float f0 = __expf(mM[0] - mn0);
        const float f1 = __expf(mM[1] - mn1);
        mM[0] = mn0; mM[1] = mn1;

        float rs0 = 0.f, rs1 = 0.f;
        #pragma unroll
        for (int nt = 0; nt < 8; nt++) {
            const __half2 p01 = __floats2half2_rn(__expf(sacc[nt][0] - mn0),
                                                  __expf(sacc[nt][1] - mn0));
            const __half2 p23 = __floats2half2_rn(__expf(sacc[nt][2] - mn1),
                                                  __expf(sacc[nt][3] - mn1));
            *(__half2*)&Psh[(m0 + qr)     * DPH + nt * 8 + 2 * qc] = p01;
            *(__half2*)&Psh[(m0 + qr + 8) * DPH + nt * 8 + 2 * qc] = p23;
            const float2 f01 = __half22float2(p01);
            const float2 f23 = __half22float2(p23);
            rs0 += f01.x + f01.y; rs1 += f23.x + f23.y;
        }
        #pragma unroll
        for (int off = 1; off < 4; off <<= 1) {
            rs0 += __shfl_xor_sync(0xffffffffu, rs0, off);
            rs1 += __shfl_xor_sync(0xffffffffu, rs1, off);
        }
        lL[0] = lL[0] * f0 + rs0;
        lL[1] = lL[1] * f1 + rs1;
        #pragma unroll
        for (int nt = 0; nt < 8; nt++) {
            oacc[nt][0] *= f0; oacc[nt][1] *= f0;
            oacc[nt][2] *= f1; oacc[nt][3] *= f1;
        }
        __syncwarp();

        tile_mma_pv(pAddr, vAddr, oacc);
    }

    // ---- compressive memory attention ----
    __syncthreads();
    issue_kv(kBase, vBase, memp + h * 64, memp + h * 64, CDIM, tid);
    asm volatile("cp.async.commit_group;");
    asm volatile("cp.async.wait_group 0;");
    __syncthreads();

    float sacc[8][4];
    #pragma unroll
    for (int nt = 0; nt < 8; nt++)
        #pragma unroll
        for (int r = 0; r < 4; r++) sacc[nt][r] = 0.f;
    tile_mma_qk(qAddr, kBase + kFragOff, sacc);

    float mx0 = -1e30f, mx1 = -1e30f;
    #pragma unroll
    for (int nt = 0; nt < 8; nt++) {
        mx0 = fmaxf(mx0, fmaxf(sacc[nt][0], sacc[nt][1]));
        mx1 = fmaxf(mx1, fmaxf(sacc[nt][2], sacc[nt][3]));
    }
    #pragma unroll
    for (int off = 1; off < 4; off <<= 1) {
        mx0 = fmaxf(mx0, __shfl_xor_sync(0xffffffffu, mx0, off));
        mx1 = fmaxf(mx1, __shfl_xor_sync(0xffffffffu, mx1, off));
    }
    float rs0 = 0.f, rs1 = 0.f;
    #pragma unroll
    for (int nt = 0; nt < 8; nt++) {
        const __half2 p01 = __floats2half2_rn(__expf(sacc[nt][0] - mx0),
                                              __expf(sacc[nt][1] - mx0));
        const __half2 p23 = __floats2half2_rn(__expf(sacc[nt][2] - mx1),
                                              __expf(sacc[nt][3] - mx1));
        *(__half2*)&Psh[(m0 + qr)     * DPH + nt * 8 + 2 * qc] = p01;
        *(__half2*)&Psh[(m0 + qr + 8) * DPH + nt * 8 + 2 * qc] = p23;
        const float2 f01 = __half22float2(p01);
        const float2 f23 = __half22float2(p23);
        rs0 += f01.x + f01.y; rs1 += f23.x + f23.y;
    }
    #pragma unroll
    for (int off = 1; off < 4; off <<= 1) {
        rs0 += __shfl_xor_sync(0xffffffffu, rs0, off);
        rs1 += __shfl_xor_sync(0xffffffffu, rs1, off);
    }
    __syncwarp();

    float oacc2[8][4];
    #pragma unroll
    for (int nt = 0; nt < 8; nt++)
        #pragma unroll
        for (int r = 0; r < 4; r++) oacc2[nt][r] = 0.f;
    tile_mma_pv(pAddr, vBase + vFragOff, oacc2);

    const float i0 = 1.f / lL[0], i1 = 1.f / lL[1];
    const float j0 = 1.f / rs0,   j1 = 1.f / rs1;
    #pragma unroll
    for (int nt = 0; nt < 8; nt++) {
        const int col = h * 64 + nt * 8 + 2 * qc;
        const int r0 = b * TSEQ + row0 + m0 + qr;
        *(__half2*)(out + (size_t)r0 * CDIM + col) =
            __floats2half2_rn(oacc[nt][0] * i0 + oacc2[nt][0] * j0,
                              oacc[nt][1] * i0 + oacc2[nt][1] * j0);
        *(__half2*)(out + (size_t)(r0 + 8) * CDIM + col) =
            __floats2half2_rn(oacc[nt][2] * i1 + oacc2[nt][2] * j1,
                              oacc[nt][3] * i1 + oacc2[nt][3] * j1);
    }
}

// ---------------- launch ----------------
extern "C" void kernel_launch(void* const* d_in, const int* in_sizes, int n_in,
                              void* d_out, int out_size)
{
    const float* x      = (const float*)d_in[0];
    const float* memory = (const float*)d_in[1];
    const float* ln1_g  = (const float*)d_in[2];
    const float* ln1_b  = (const float*)d_in[3];
    const float* w_qkv  = (const float*)d_in[4];
    const float* b_qkv  = (const float*)d_in[5];
    const float* w_out  = (const float*)d_in[6];
    const float* b_out  = (const float*)d_in[7];
    const float* w_mem  = (const float*)d_in[8];
    const float* b_mem  = (const float*)d_in[9];
    const float* ln2_g  = (const float*)d_in[10];
    const float* ln2_b  = (const float*)d_in[11];
    const float* w_fc1  = (const float*)d_in[12];
    const float* b_fc1  = (const float*)d_in[13];
    const float* w_fc2  = (const float*)d_in[14];
    const float* b_fc2  = (const float*)d_in[15];
    float* out = (float*)d_out;

    __half *pH, *pQKV, *pMEMP, *pATTN, *pH2, *pHID;
    __half *pWQKVT, *pWOUTT, *pWFC1T, *pWFC2T;
    float *pX1;
    cudaGetSymbolAddress((void**)&pH,     g_H);
    cudaGetSymbolAddress((void**)&pQKV,   g_QKV);
    cudaGetSymbolAddress((void**)&pMEMP,  g_MEMP);
    cudaGetSymbolAddress((void**)&pATTN,  g_ATTN);
    cudaGetSymbolAddress((void**)&pX1,    g_X1);
    cudaGetSymbolAddress((void**)&pH2,    g_H2);
    cudaGetSymbolAddress((void**)&pHID,   g_HID);
    cudaGetSymbolAddress((void**)&pWQKVT, g_WQKVT);
    cudaGetSymbolAddress((void**)&pWOUTT, g_WOUTT);
    cudaGetSymbolAddress((void**)&pWFC1T, g_WFC1T);
    cudaGetSymbolAddress((void**)&pWFC2T, g_WFC2T);

    cudaFuncSetAttribute(attn_mma, cudaFuncAttributeMaxDynamicSharedMemorySize, ATTN_SMEM);
    cudaFuncSetAttribute(gemm_mma<0, __half>, cudaFuncAttributeMaxDynamicSharedMemorySize, GSMEM_BYTES);
    cudaFuncSetAttribute(gemm_mma<1, float>,  cudaFuncAttributeMaxDynamicSharedMemorySize, GSMEM_BYTES);
    cudaFuncSetAttribute(gemm_mma<2, __half>, cudaFuncAttributeMaxDynamicSharedMemorySize, GSMEM_BYTES);

    const int ROWS = BATCH * TSEQ;  // 4096

    prep_kernel<<<PREP_BLOCKS, 256>>>(w_qkv, w_out, w_fc1, w_fc2,
                                      pWQKVT, pWOUTT, pWFC1T, pWFC2T,
                                      x, ln1_g, ln1_b, pH,
                                      memory, w_mem, b_mem, pMEMP);

    gemm_mma<0, __half><<<dim3(3 * CDIM / 128, ROWS / 128), 256, GSMEM_BYTES>>>(
        pH, pWQKVT, b_qkv, nullptr, pQKV, ROWS, 3 * CDIM, CDIM);

    attn_mma<<<dim3(TSEQ / QT, NHEAD, BATCH), 256, ATTN_SMEM>>>(pQKV, pMEMP, pATTN);

    gemm_mma<1, float><<<dim3(CDIM / 128, ROWS / 128), 256, GSMEM_BYTES>>>(
        pATTN, pWOUTT, b_out, x, pX1, ROWS, CDIM, CDIM);

    ln_kernel<<<ROWS, 256>>>(pX1, ln2_g, ln2_b, pH2);

    gemm_mma<2, __half><<<dim3(HIDDEN / 128, ROWS / 128), 256, GSMEM_BYTES>>>(
        pH2, pWFC1T, b_fc1, nullptr, pHID, ROWS, HIDDEN, CDIM);

    gemm_mma<1, float><<<dim3(CDIM / 128, ROWS / 128), 256, GSMEM_BYTES>>>(
        pHID, pWFC2T, b_fc2, pX1, out, ROWS, CDIM, HIDDEN);
}

// round 15
// speedup vs baseline: 1.1807x; 1.0314x over previous
#include <cuda_runtime.h>
#include <cuda_fp16.h>
#include <math.h>
#include <stdint.h>

#define CDIM   1024
#define TSEQ   2048
#define BATCH  2
#define NHEAD  16
#define HDIM   64
#define MMEM   64
#define HIDDEN 4096

// ---------------- scratch (device globals; no allocation) ----------------
__device__ __half g_H    [BATCH*TSEQ*CDIM];
__device__ __half g_QKV  [BATCH*TSEQ*3*CDIM];
__device__ __half g_MEMP [MMEM*CDIM];
__device__ __half g_ATTN [BATCH*TSEQ*CDIM];
__device__ float  g_X1   [BATCH*TSEQ*CDIM];
__device__ __half g_H2   [BATCH*TSEQ*CDIM];
__device__ __half g_HID  [BATCH*TSEQ*HIDDEN];
__device__ __half g_WQKVT[3*CDIM*CDIM];
__device__ __half g_WOUTT[CDIM*CDIM];
__device__ __half g_WFC1T[HIDDEN*CDIM];
__device__ __half g_WFC2T[CDIM*HIDDEN];

__device__ __forceinline__ uint32_t smem_u32(const void* p) {
    uint32_t a;
    asm("{ .reg .u64 t; cvta.to.shared.u64 t, %1; cvt.u32.u64 %0, t; }" : "=r"(a) : "l"(p));
    return a;
}
__device__ __forceinline__ void cp16(uint32_t dst, const void* src) {
    asm volatile("cp.async.cg.shared.global [%0], [%1], 16;" :: "r"(dst), "l"(src));
}
__device__ __forceinline__ void mma_f16(float* c, uint32_t a0, uint32_t a1,
                                        uint32_t a2, uint32_t a3,
                                        uint32_t b0, uint32_t b1)
{
    asm volatile(
        "mma.sync.aligned.m16n8k16.row.col.f32.f16.f16.f32 "
        "{%0,%1,%2,%3}, {%4,%5,%6,%7}, {%8,%9}, {%0,%1,%2,%3};"
        : "+f"(c[0]), "+f"(c[1]), "+f"(c[2]), "+f"(c[3])
        : "r"(a0), "r"(a1), "r"(a2), "r"(a3), "r"(b0), "r"(b1));
}
__device__ __forceinline__ void ldsm4(uint32_t* r, uint32_t addr) {
    asm volatile("ldmatrix.sync.aligned.m8n8.x4.shared.b16 {%0,%1,%2,%3}, [%4];"
        : "=r"(r[0]), "=r"(r[1]), "=r"(r[2]), "=r"(r[3]) : "r"(addr));
}
__device__ __forceinline__ void ldsm4t(uint32_t* r, uint32_t addr) {
    asm volatile("ldmatrix.sync.aligned.m8n8.x4.trans.shared.b16 {%0,%1,%2,%3}, [%4];"
        : "=r"(r[0]), "=r"(r[1]), "=r"(r[2]), "=r"(r[3]) : "r"(addr));
}

// ---------------- LayerNorm body ----------------
__device__ __forceinline__ void ln_body(const float* __restrict__ x, const float* __restrict__ g,
                                        const float* __restrict__ b, __half* __restrict__ y,
                                        int row, int tid, float* red)
{
    const float4 v = ((const float4*)(x + (size_t)row * CDIM))[tid];
    float s  = v.x + v.y + v.z + v.w;
    float ss = v.x*v.x + v.y*v.y + v.z*v.z + v.w*v.w;
    #pragma unroll
    for (int off = 16; off; off >>= 1) {
        s  += __shfl_xor_sync(0xffffffffu, s,  off);
        ss += __shfl_xor_sync(0xffffffffu, ss, off);
    }
    if ((tid & 31) == 0) { red[tid >> 5] = s; red[8 + (tid >> 5)] = ss; }
    __syncthreads();
    if (tid == 0) {
        float ts = 0.f, tss = 0.f;
        #pragma unroll
        for (int w = 0; w < 8; w++) { ts += red[w]; tss += red[8 + w]; }
        red[16] = ts; red[17] = tss;
    }
    __syncthreads();
    const float mu  = red[16] * (1.f / CDIM);
    const float var = red[17] * (1.f / CDIM) - mu * mu;
    const float inv = rsqrtf(var + 1e-5f);
    const float4 gv = ((const float4*)g)[tid];
    const float4 bv = ((const float4*)b)[tid];
    __half2 h01 = __floats2half2_rn((v.x - mu) * inv * gv.x + bv.x,
                                    (v.y - mu) * inv * gv.y + bv.y);
    __half2 h23 = __floats2half2_rn((v.z - mu) * inv * gv.z + bv.z,
                                    (v.w - mu) * inv * gv.w + bv.w);
    __half2* yp = (__half2*)(y + (size_t)row * CDIM + tid * 4);
    yp[0] = h01; yp[1] = h23;
}

__global__ __launch_bounds__(256)
void ln_kernel(const float* __restrict__ x, const float* __restrict__ g,
               const float* __restrict__ b, __half* __restrict__ y)
{
    __shared__ float red[18];
    ln_body(x, g, b, y, blockIdx.x, threadIdx.x, red);
}

// ---------------- transpose body ----------------
__device__ __forceinline__ void transpose_body(const float* __restrict__ S, __half* __restrict__ D,
                                               int K, int N, int lb, int tid, char* buf)
{
    float (*t)[33] = (float(*)[33])buf;
    const int gx = N / 32;
    const int bx = (lb % gx) * 32;
    const int by = (lb / gx) * 32;
    const int x = tid & 31, y = tid >> 5;
    #pragma unroll
    for (int i = 0; i < 32; i += 8)
        t[y + i][x] = S[(size_t)(by + y + i) * N + bx + x];
    __syncthreads();
    #pragma unroll
    for (int i = 0; i < 32; i += 8)
        D[(size_t)(bx + y + i) * K + by + x] = __float2half_rn(t[x][y + i]);
}

// ---------------- memproj body ----------------
__device__ __forceinline__ void memproj_body(const float* __restrict__ A, const float* __restrict__ B,
                                             const float* __restrict__ bias, __half* __restrict__ C,
                                             int lb, int tid, char* buf)
{
    float (*Ast)[64] = (float(*)[64])buf;
    float (*Bs)[64]  = (float(*)[64])(buf + 4096);
    const int tx = tid & 15, ty = tid >> 4;
    const int bn = lb * 64;
    const int ar = tid >> 2, ak = (tid & 3) << 2;
    const int bk = tid >> 4, bc = (tid & 15) << 2;

    float acc[4][4];
    #pragma unroll
    for (int i = 0; i < 4; i++)
        #pragma unroll
        for (int j = 0; j < 4; j++) acc[i][j] = 0.f;

    for (int k0 = 0; k0 < CDIM; k0 += 16) {
        const float4 av = *(const float4*)(A + (size_t)ar * CDIM + k0 + ak);
        const float4 bv = *(const float4*)(B + (size_t)(k0 + bk) * CDIM + bn + bc);
        __syncthreads();
        Ast[ak + 0][ar] = av.x;
        Ast[ak + 1][ar] = av.y;
        Ast[ak + 2][ar] = av.z;
        Ast[ak + 3][ar] = av.w;
        *(float4*)&Bs[bk][bc] = bv;
        __syncthreads();
        #pragma unroll
        for (int kk = 0; kk < 16; kk++) {
            const float4 a = *(const float4*)&Ast[kk][ty * 4];
            const float4 b = *(const float4*)&Bs[kk][tx * 4];
            const float arr[4] = {a.x, a.y, a.z, a.w};
            const float brr[4] = {b.x, b.y, b.z, b.w};
            #pragma unroll
            for (int i = 0; i < 4; i++)
                #pragma unroll
                for (int j = 0; j < 4; j++)
                    acc[i][j] = fmaf(arr[i], brr[j], acc[i][j]);
        }
    }
    #pragma unroll
    for (int i = 0; i < 4; i++) {
        const int col = bn + tx * 4;
        const float4 bsv = *(const float4*)(bias + col);
        __half2* cp = (__half2*)(C + (size_t)(ty * 4 + i) * CDIM + col);
        cp[0] = __floats2half2_rn(acc[i][0] + bsv.x, acc[i][1] + bsv.y);
        cp[1] = __floats2half2_rn(acc[i][2] + bsv.z, acc[i][3] + bsv.w);
    }
}

// ---------------- fused prep ----------------
#define PREP_BLOCKS 16400

__global__ __launch_bounds__(256)
void prep_kernel(const float* __restrict__ w_qkv, const float* __restrict__ w_out,
                 const float* __restrict__ w_fc1, const float* __restrict__ w_fc2,
                 __half* __restrict__ WQKVT, __half* __restrict__ WOUTT,
                 __half* __restrict__ WFC1T, __half* __restrict__ WFC2T,
                 const float* __restrict__ x, const float* __restrict__ ln1_g,
                 const float* __restrict__ ln1_b, __half* __restrict__ H,
                 const float* __restrict__ memory, const float* __restrict__ w_mem,
                 const float* __restrict__ b_mem, __half* __restrict__ MEMP)
{
    __shared__ char buf[8448];
    const int bid = blockIdx.x;
    const int tid = threadIdx.x;

    if (bid < 3072) {
        transpose_body(w_qkv, WQKVT, CDIM, 3 * CDIM, bid, tid, buf);
    } else if (bid < 4096) {
        transpose_body(w_out, WOUTT, CDIM, CDIM, bid - 3072, tid, buf);
    } else if (bid < 8192) {
        transpose_body(w_fc1, WFC1T, CDIM, HIDDEN, bid - 4096, tid, buf);
    } else if (bid < 12288) {
        transpose_body(w_fc2, WFC2T, HIDDEN, CDIM, bid - 8192, tid, buf);
    } else if (bid < 16384) {
        ln_body(x, ln1_g, ln1_b, H, bid - 12288, tid, (float*)buf);
    } else {
        memproj_body(memory, w_mem, b_mem, MEMP, bid - 16384, tid, buf);
    }
}

// ---------------- fp16 mma GEMM: BK=32, 4 stages, wait<=2 (2-chunk prefetch lead) ----------------
#define SKEWH 40
#define GST   (128 * SKEWH)
#define GSMEM_BYTES (4 * 2 * GST * 2)   // 81920

template<int EPI, typename TOut>
__global__ __launch_bounds__(256, 2)
void gemm_mma(const __half* __restrict__ A, const __half* __restrict__ Bt,
              const float* __restrict__ bias, const float* __restrict__ res,
              TOut* __restrict__ C, int M, int N, int K)
{
    extern __shared__ __half sgm[];
    const uint32_t sAa = smem_u32(sgm);
    const uint32_t sBa = sAa + 4u * GST * 2u;

    const int tid = threadIdx.x;
    const int wid = tid >> 5, lane = tid & 31;
    const int wm = (wid & 1) * 64;
    const int wn = (wid >> 1) * 32;
    const int bm = blockIdx.y * 128;
    const int bn = blockIdx.x * 128;

    // loader mapping identical to R12 (proven)
    const int lrow = tid >> 2;
    const int lcol = (tid & 3) << 3;
    const __half* Ap = A  + (size_t)(bm + lrow) * K + lcol;
    const __half* Bp = Bt + (size_t)(bn + lrow) * K + lcol;
    const uint32_t soff = ((uint32_t)lrow * SKEWH + (uint32_t)lcol) * 2u;

    const int qr = lane >> 2;
    const int qc = lane & 3;
    const int nchunk = K / 32;

    const int arow = lane & 15;
    const int acol = (lane >> 4) * 8;
    const int brow = (lane & 7) + ((lane & 16) ? 8 : 0);
    const int bcol = ((lane >> 3) & 1) * 8;
    const uint32_t aoffb = ((uint32_t)(wm + arow) * SKEWH + acol) * 2u;
    const uint32_t boffb = ((uint32_t)(wn + brow) * SKEWH + bcol) * 2u;

    float acc[4][4][4];
    #pragma unroll
    for (int i = 0; i < 4; i++)
        #pragma unroll
        for (int j = 0; j < 4; j++)
            #pragma unroll
            for (int r = 0; r < 4; r++) acc[i][j][r] = 0.f;

    // prologue: chunks 0,1,2 into stages 0,1,2 (one commit group each)
    #pragma unroll
    for (int pc = 0; pc < 3; pc++) {
        const uint32_t sb = (uint32_t)pc * GST * 2u;
        #pragma unroll
        for (int p = 0; p < 2; p++) {
            cp16(sAa + sb + soff + p * 64 * SKEWH * 2, Ap + (size_t)(p * 64) * K + pc * 32);
            cp16(sBa + sb + soff + p * 64 * SKEWH * 2, Bp + (size_t)(p * 64) * K + pc * 32);
        }
        asm volatile("cp.async.commit_group;");
    }

    for (int ch = 0; ch < nchunk; ch++) {
        asm volatile("cp.async.wait_group 2;");
        __syncthreads();   // chunk ch visible; warps past iter ch-1 -> stage (ch+3)&3 free

        if (ch + 3 < nchunk) {
            const uint32_t sb = (uint32_t)((ch + 3) & 3) * GST * 2u;
            const int k0 = (ch + 3) * 32;
            #pragma unroll
            for (int p = 0; p < 2; p++) {
                cp16(sAa + sb + soff + p * 64 * SKEWH * 2, Ap + (size_t)(p * 64) * K + k0);
                cp16(sBa + sb + soff + p * 64 * SKEWH * 2, Bp + (size_t)(p * 64) * K + k0);
            }
        }
        asm volatile("cp.async.commit_group;");

        const uint32_t aB = sAa + (uint32_t)(ch & 3) * GST * 2u + aoffb;
        const uint32_t bB = sBa + (uint32_t)(ch & 3) * GST * 2u + boffb;

        #pragma unroll
        for (int ks = 0; ks < 2; ks++) {
            const uint32_t kb = ks * 32;
            uint32_t bb0[4], bb1[4];
            ldsm4(bb0, bB + kb);
            ldsm4(bb1, bB + 16u * SKEWH * 2u + kb);
            #pragma unroll
            for (int mt = 0; mt < 4; mt++) {
                uint32_t a[4];
                ldsm4(a, aB + (uint32_t)mt * 16u * SKEWH * 2u + kb);
                mma_f16(acc[mt][0], a[0], a[1], a[2], a[3], bb0[0], bb0[1]);
                mma_f16(acc[mt][1], a[0], a[1], a[2], a[3], bb0[2], bb0[3]);
                mma_f16(acc[mt][2], a[0], a[1], a[2], a[3], bb1[0], bb1[1]);
                mma_f16(acc[mt][3], a[0], a[1], a[2], a[3], bb1[2], bb1[3]);
            }
        }
    }

    #pragma unroll
    for (int mt = 0; mt < 4; mt++) {
        #pragma unroll
        for (int half_ = 0; half_ < 2; half_++) {
            const int row = bm + wm + mt * 16 + qr + half_ * 8;
            const float* Rrow = res + (size_t)row * N;
            #pragma unroll
            for (int nt = 0; nt < 4; nt++) {
                const int col = bn + wn + nt * 8 + qc * 2;
                float v0 = acc[mt][nt][half_ * 2 + 0] + bias[col];
                float v1 = acc[mt][nt][half_ * 2 + 1] + bias[col + 1];
                if (EPI == 1) {
                    const float2 rv = *(const float2*)(Rrow + col);
                    v0 += rv.x; v1 += rv.y;
                }
                if (EPI == 2) {
                    v0 = 0.5f * v0 * (1.0f + erff(v0 * 0.70710678118654752f));
                    v1 = 0.5f * v1 * (1.0f + erff(v1 * 0.70710678118654752f));
                }
                TOut* Crow = C + (size_t)row * N;
                if (sizeof(TOut) == 2) {
                    *(__half2*)((__half*)Crow + col) = __floats2half2_rn(v0, v1);
                } else {
                    *(float2*)((float*)Crow + col) = make_float2(v0, v1);
                }
            }
        }
    }
}

// ---------------- fp16 mma attention (R9/R12-proven, 2-stage) ----------------
#define QT   128
#define KC   64
#define DPH  72
#define ATTN_SMEM ((128*DPH + 2*64*DPH + 2*64*DPH + 128*DPH) * 2)   // 73728

__device__ __forceinline__ void issue_kv(uint32_t kDst, uint32_t vDst,
                                         const __half* __restrict__ kSrc,
                                         const __half* __restrict__ vSrc,
                                         size_t rstride, int tid)
{
    const int r = tid >> 2;
    const uint32_t off = (uint32_t)r * DPH * 2u + (uint32_t)(tid & 3) * 32u;
    const __half* ks = kSrc + (size_t)r * rstride + (tid & 3) * 16;
    const __half* vs = vSrc + (size_t)r * rstride + (tid & 3) * 16;
    cp16(kDst + off,       ks);
    cp16(kDst + off + 16u, ks + 8);
    cp16(vDst + off,       vs);
    cp16(vDst + off + 16u, vs + 8);
}

__device__ __forceinline__ void tile_mma_qk(uint32_t aAddr, uint32_t bAddr, float acc[8][4])
{
    #pragma unroll
    for (int ks = 0; ks < 4; ks++) {
        const uint32_t kb = ks * 32;
        uint32_t a[4];
        ldsm4(a, aAddr + kb);
        #pragma unroll
        for (int p = 0; p < 4; p++) {
            uint32_t bb[4];
            ldsm4(bb, bAddr + (uint32_t)p * 16u * DPH * 2u + kb);
            mma_f16(acc[2 * p],     a[0], a[1], a[2], a[3], bb[0], bb[1]);
            mma_f16(acc[2 * p + 1], a[0], a[1], a[2], a[3], bb[2], bb[3]);
        }
    }
}

__device__ __forceinline__ void tile_mma_pv(uint32_t aAddr, uint32_t bAddr, float acc[8][4])
{
    #pragma unroll
    for (int ks = 0; ks < 4; ks++) {
        const uint32_t kb = ks * 32;
        const uint32_t vb = (uint32_t)ks * 16u * DPH * 2u;
        uint32_t a[4];
        ldsm4(a, aAddr + kb);
        #pragma unroll
        for (int p = 0; p < 4; p++) {
            uint32_t bb[4];
            ldsm4t(bb, bAddr + vb + (uint32_t)p * 32u);
            mma_f16(acc[2 * p],     a[0], a[1], a[2], a[3], bb[0], bb[1]);
            mma_f16(acc[2 * p + 1], a[0], a[1], a[2], a[3], bb[2], bb[3]);
        }
    }
}

__global__ __launch_bounds__(256)
void attn_mma(const __half* __restrict__ qkv, const __half* __restrict__ memp,
              __half* __restrict__ out)
{
    extern __shared__ __half smh[];
    __half* Qsh = smh;
    __half* Kst = smh + 128 * DPH;
    __half* Vst = Kst + 2 * 64 * DPH;
    __half* Psh = Vst + 2 * 64 * DPH;

    const int tid  = threadIdx.x;
    const int wid  = tid >> 5, lane = tid & 31;
    const int qr   = lane >> 2, qc = lane & 3;
    const int m0   = wid * 16;
    const int h    = blockIdx.y, b = blockIdx.z;
    const int row0 = blockIdx.x * QT;

    const int arow = lane & 15;
    const int acol = (lane >> 4) * 8;
    const int brow = (lane & 7) + ((lane & 16) ? 8 : 0);
    const int bcol = ((lane >> 3) & 1) * 8;

    const uint32_t qAddr = smem_u32(Qsh) + ((uint32_t)(m0 + arow) * DPH + acol) * 2u;
    const uint32_t pAddr = smem_u32(Psh) + ((uint32_t)(m0 + arow) * DPH + acol) * 2u;
    const uint32_t kBase = smem_u32(Kst);
    const uint32_t vBase = smem_u32(Vst);
    const uint32_t kFragOff = ((uint32_t)brow * DPH + bcol) * 2u;
    const uint32_t vFragOff = ((uint32_t)arow * DPH + acol) * 2u;
    const uint32_t stageB = 64u * DPH * 2u;

    const __half* kSrc0 = qkv + ((size_t)(b * TSEQ)) * (3 * CDIM) + CDIM + h * 64;
    const __half* vSrc0 = qkv + ((size_t)(b * TSEQ)) * (3 * CDIM) + 2 * CDIM + h * 64;

    {
        const int r  = tid >> 1;
        const int c0 = (tid & 1) * 32;
        const __half2 sc = __float2half2_rn(0.125f);
        const __half2* qp = (const __half2*)(qkv + ((size_t)(b * TSEQ + row0 + r)) * (3 * CDIM) + h * 64 + c0);
        __half2* qd = (__half2*)&Qsh[r * DPH + c0];
        #pragma unroll
        for (int j = 0; j < 16; j++)
            qd[j] = __hmul2(qp[j], sc);
    }

    issue_kv(kBase, vBase, kSrc0, vSrc0, 3 * CDIM, tid);
    asm volatile("cp.async.commit_group;");

    float mM[2] = {-1e30f, -1e30f};
    float lL[2] = {0.f, 0.f};
    float oacc[8][4];
    #pragma unroll
    for (int nt = 0; nt < 8; nt++)
        #pragma unroll
        for (int r = 0; r < 4; r++) oacc[nt][r] = 0.f;

    const int NCH = TSEQ / KC;
    for (int ci = 0; ci < NCH; ci++) {
        asm volatile("cp.async.wait_group 0;");
        __syncthreads();

        if (ci + 1 < NCH) {
            const int sn = (ci + 1) & 1;
            issue_kv(kBase + (uint32_t)sn * stageB, vBase + (uint32_t)sn * stageB,
                     kSrc0 + (size_t)(ci + 1) * KC * (3 * CDIM),
                     vSrc0 + (size_t)(ci + 1) * KC * (3 * CDIM),
                     3 * CDIM, tid);
        }
        asm volatile("cp.async.commit_group;");

        const int st = ci & 1;
        const uint32_t kAddr = kBase + (uint32_t)st * stageB + kFragOff;
        const uint32_t vAddr = vBase + (uint32_t)st * stageB + vFragOff;

        float sacc[8][4];
        #pragma unroll
        for (int nt = 0; nt < 8; nt++)
            #pragma unroll
            for (int r = 0; r < 4; r++) sacc[nt][r] = 0.f;
        tile_mma_qk(qAddr, kAddr, sacc);

        float mx0 = -1e30f, mx1 = -1e30f;
        #pragma unroll
        for (int nt = 0; nt < 8; nt++) {
            mx0 = fmaxf(mx0, fmaxf(sacc[nt][0], sacc[nt][1]));
            mx1 = fmaxf(mx1, fmaxf(sacc[nt][2], sacc[nt][3]));
        }
        #pragma unroll
        for (int off = 1; off < 4; off <<= 1) {
            mx0 = fmaxf(mx0, __shfl_xor_sync(0xffffffffu, mx0, off));
            mx1 = fmaxf(mx1, __shfl_xor_sync(0xffffffffu, mx1, off));
        }
        const float mn0 = fmaxf(mM[0], mx0);
        const float mn1 = fmaxf(mM[1], mx1);
        const float f0 = __expf(mM[0] - mn0);
        const float f1 = __expf(mM[1] - mn1);
        mM[0] = mn0; mM[1] = mn1;

        float rs0 = 0.f, rs1 = 0.f;
        #pragma unroll
        for (int nt = 0; nt < 8; nt++) {
            const __half2 p01 = __floats2half2_rn(__expf(sacc[nt][0] - mn0),
                                                  __expf(sacc[nt][1] - mn0));
            const __half2 p23 = __floats2half2_rn(__expf(sacc[nt][2] - mn1),
                                                  __expf(sacc[nt][3] - mn1));
            *(__half2*)&Psh[(m0 + qr)     * DPH + nt * 8 + 2 * qc] = p01;
            *(__half2*)&Psh[(m0 + qr + 8) * DPH + nt * 8 + 2 * qc] = p23;
            const float2 f01 = __half22float2(p01);
            const float2 f23 = __half22float2(p23);
            rs0 += f01.x + f01.y; rs1 += f23.x + f23.y;
        }
        #pragma unroll
        for (int off = 1; off < 4; off <<= 1) {
            rs0 += __shfl_xor_sync(0xffffffffu, rs0, off);
            rs1 += __shfl_xor_sync(0xffffffffu, rs1, off);
        }
        lL[0] = lL[0] * f0 + rs0;
        lL[1] = lL[1] * f1 + rs1;
        #pragma unroll
        for (int nt = 0; nt < 8; nt++) {
            oacc[nt][0] *= f0; oacc[nt][1] *= f0;
            oacc[nt][2] *= f1; oacc[nt][3] *= f1;
        }
        __syncwarp();

        tile_mma_pv(pAddr, vAddr, oacc);
    }

    // ---- compressive memory attention ----
    __syncthreads();
    issue_kv(kBase, vBase, memp + h * 64, memp + h * 64, CDIM, tid);
    asm volatile("cp.async.commit_group;");
    asm volatile("cp.async.wait_group 0;");
    __syncthreads();

    float sacc[8][4];
    #pragma unroll
    for (int nt = 0; nt < 8; nt++)
        #pragma unroll
        for (int r = 0; r < 4; r++) sacc[nt][r] = 0.f;
    tile_mma_qk(qAddr, kBase + kFragOff, sacc);

    float mx0 = -1e30f, mx1 = -1e30f;
    #pragma unroll
    for (int nt = 0; nt < 8; nt++) {
        mx0 = fmaxf(mx0, fmaxf(sacc[nt][0], sacc[nt][1]));
        mx1 = fmaxf(mx1, fmaxf(sacc[nt][2], sacc[nt][3]));
    }
    #pragma unroll
    for (int off = 1; off < 4; off <<= 1) {
        mx0 = fmaxf(mx0, __shfl_xor_sync(0xffffffffu, mx0, off));
        mx1 = fmaxf(mx1, __shfl_xor_sync(0xffffffffu, mx1, off));
    }
    float rs0 = 0.f, rs1 = 0.f;
    #pragma unroll
    for (int nt = 0; nt < 8; nt++) {
        const __half2 p01 = __floats2half2_rn(__expf(sacc[nt][0] - mx0),
                                              __expf(sacc[nt][1] - mx0));
        const __half2 p23 = __floats2half2_rn(__expf(sacc[nt][2] - mx1),
                                              __expf(sacc[nt][3] - mx1));
        *(__half2*)&Psh[(m0 + qr)     * DPH + nt * 8 + 2 * qc] = p01;
        *(__half2*)&Psh[(m0 + qr + 8) * DPH + nt * 8 + 2 * qc] = p23;
        const float2 f01 = __half22float2(p01);
        const float2 f23 = __half22float2(p23);
        rs0 += f01.x + f01.y; rs1 += f23.x + f23.y;
    }
    #pragma unroll
    for (int off = 1; off < 4; off <<= 1) {
        rs0 += __shfl_xor_sync(0xffffffffu, rs0, off);
        rs1 += __shfl_xor_sync(0xffffffffu, rs1, off);
    }
    __syncwarp();

    float oacc2[8][4];
    #pragma unroll
    for (int nt = 0; nt < 8; nt++)
        #pragma unroll
        for (int r = 0; r < 4; r++) oacc2[nt][r] = 0.f;
    tile_mma_pv(pAddr, vBase + vFragOff, oacc2);

    const float i0 = 1.f / lL[0], i1 = 1.f / lL[1];
    const float j0 = 1.f / rs0,   j1 = 1.f / rs1;
    #pragma unroll
    for (int nt = 0; nt < 8; nt++) {
        const int col = h * 64 + nt * 8 + 2 * qc;
        const int r0 = b * TSEQ + row0 + m0 + qr;
        *(__half2*)(out + (size_t)r0 * CDIM + col) =
            __floats2half2_rn(oacc[nt][0] * i0 + oacc2[nt][0] * j0,
                              oacc[nt][1] * i0 + oacc2[nt][1] * j0);
        *(__half2*)(out + (size_t)(r0 + 8) * CDIM + col) =
            __floats2half2_rn(oacc[nt][2] * i1 + oacc2[nt][2] * j1,
                              oacc[nt][3] * i1 + oacc2[nt][3] * j1);
    }
}

// ---------------- launch ----------------
extern "C" void kernel_launch(void* const* d_in, const int* in_sizes, int n_in,
                              void* d_out, int out_size)
{
    const float* x      = (const float*)d_in[0];
    const float* memory = (const float*)d_in[1];
    const float* ln1_g  = (const float*)d_in[2];
    const float* ln1_b  = (const float*)d_in[3];
    const float* w_qkv  = (const float*)d_in[4];
    const float* b_qkv  = (const float*)d_in[5];
    const float* w_out  = (const float*)d_in[6];
    const float* b_out  = (const float*)d_in[7];
    const float* w_mem  = (const float*)d_in[8];
    const float* b_mem  = (const float*)d_in[9];
    const float* ln2_g  = (const float*)d_in[10];
    const float* ln2_b  = (const float*)d_in[11];
    const float* w_fc1  = (const float*)d_in[12];
    const float* b_fc1  = (const float*)d_in[13];
    const float* w_fc2  = (const float*)d_in[14];
    const float* b_fc2  = (const float*)d_in[15];
    float* out = (float*)d_out;

    __half *pH, *pQKV, *pMEMP, *pATTN, *pH2, *pHID;
    __half *pWQKVT, *pWOUTT, *pWFC1T, *pWFC2T;
    float *pX1;
    cudaGetSymbolAddress((void**)&pH,     g_H);
    cudaGetSymbolAddress((void**)&pQKV,   g_QKV);
    cudaGetSymbolAddress((void**)&pMEMP,  g_MEMP);
    cudaGetSymbolAddress((void**)&pATTN,  g_ATTN);
    cudaGetSymbolAddress((void**)&pX1,    g_X1);
    cudaGetSymbolAddress((void**)&pH2,    g_H2);
    cudaGetSymbolAddress((void**)&pHID,   g_HID);
    cudaGetSymbolAddress((void**)&pWQKVT, g_WQKVT);
    cudaGetSymbolAddress((void**)&pWOUTT, g_WOUTT);
    cudaGetSymbolAddress((void**)&pWFC1T, g_WFC1T);
    cudaGetSymbolAddress((void**)&pWFC2T, g_WFC2T);

    cudaFuncSetAttribute(attn_mma, cudaFuncAttributeMaxDynamicSharedMemorySize, ATTN_SMEM);
    cudaFuncSetAttribute(gemm_mma<0, __half>, cudaFuncAttributeMaxDynamicSharedMemorySize, GSMEM_BYTES);
    cudaFuncSetAttribute(gemm_mma<1, float>,  cudaFuncAttributeMaxDynamicSharedMemorySize, GSMEM_BYTES);
    cudaFuncSetAttribute(gemm_mma<2, __half>, cudaFuncAttributeMaxDynamicSharedMemorySize, GSMEM_BYTES);

    const int ROWS = BATCH * TSEQ;  // 4096

    prep_kernel<<<PREP_BLOCKS, 256>>>(w_qkv, w_out, w_fc1, w_fc2,
                                      pWQKVT, pWOUTT, pWFC1T, pWFC2T,
                                      x, ln1_g, ln1_b, pH,
                                      memory, w_mem, b_mem, pMEMP);

    gemm_mma<0, __half><<<dim3(3 * CDIM / 128, ROWS / 128), 256, GSMEM_BYTES>>>(
        pH, pWQKVT, b_qkv, nullptr, pQKV, ROWS, 3 * CDIM, CDIM);

    attn_mma<<<dim3(TSEQ / QT, NHEAD, BATCH), 256, ATTN_SMEM>>>(pQKV, pMEMP, pATTN);

    gemm_mma<1, float><<<dim3(CDIM / 128, ROWS / 128), 256, GSMEM_BYTES>>>(
        pATTN, pWOUTT, b_out, x, pX1, ROWS, CDIM, CDIM);

    ln_kernel<<<ROWS, 256>>>(pX1, ln2_g, ln2_b, pH2);

    gemm_mma<2, __half><<<dim3(HIDDEN / 128, ROWS / 128), 256, GSMEM_BYTES>>>(
        pH2, pWFC1T, b_fc1, nullptr, pHID, ROWS, HIDDEN, CDIM);

    gemm_mma<1, float><<<dim3(CDIM / 128, ROWS / 128), 256, GSMEM_BYTES>>>(
        pHID, pWFC2T, b_fc2, pX1, out, ROWS, CDIM, HIDDEN);
}